// round 4
// baseline (speedup 1.0000x reference)
#include <cuda_runtime.h>
#include <math.h>

#define NB 8
#define TT 2048
#define BT (NB*TT)
#define INF 8
#define DM 256
#define ED 512
#define NST 16
#define DTR 16
#define NL 2

// ---- scratch (device globals: allowed; no dynamic allocation) ----
__device__ float g_h[BT*DM];       // residual stream
__device__ float g_u[BT*DM];       // rmsnormed input to mixer
__device__ float g_xz[(size_t)BT*2*ED]; // in_proj output [xm | z]
__device__ float g_xc[(size_t)BT*ED];   // conv+silu
__device__ float g_dbc[(size_t)BT*48];  // x_proj output: dt|B|C
__device__ float g_delta[(size_t)BT*ED];
__device__ float g_y[(size_t)BT*ED];

// ---------------- block reduction (blockDim=256) ----------------
__device__ __forceinline__ float blockReduce(float v, float* red) {
    int lane = threadIdx.x & 31, w = threadIdx.x >> 5;
#pragma unroll
    for (int o = 16; o; o >>= 1) v += __shfl_xor_sync(0xffffffffu, v, o);
    __syncthreads();                 // protect red from previous use
    if (lane == 0) red[w] = v;
    __syncthreads();
    if (w == 0) {
        float s = (lane < 8) ? red[lane] : 0.f;
#pragma unroll
        for (int o = 4; o; o >>= 1) s += __shfl_xor_sync(0xffffffffu, s, o);
        if (lane == 0) red[8] = s;
    }
    __syncthreads();
    return red[8];
}

// ---------------- K1: input proj + layernorm ----------------
__global__ void __launch_bounds__(256) k_input(
    const float* __restrict__ x, const float* __restrict__ W,
    const float* __restrict__ bias, const float* __restrict__ g,
    const float* __restrict__ be)
{
    int t = blockIdx.x, d = threadIdx.x;
    __shared__ float xs[INF];
    __shared__ float red[9];
    if (d < INF) xs[d] = x[t*INF + d];
    __syncthreads();
    float acc = bias[d];
#pragma unroll
    for (int i = 0; i < INF; i++) acc += xs[i] * W[d*INF + i];
    float mean = blockReduce(acc, red) * (1.f/DM);
    float c = acc - mean;
    float var = blockReduce(c*c, red) * (1.f/DM);
    g_h[t*DM + d] = c * rsqrtf(var + 1e-5f) * g[d] + be[d];
}

// ---------------- K2: rmsnorm h -> u ----------------
__global__ void __launch_bounds__(256) k_rms(const float* __restrict__ w)
{
    int t = blockIdx.x, d = threadIdx.x;
    __shared__ float red[9];
    float v = g_h[t*DM + d];
    float ss = blockReduce(v*v, red) * (1.f/DM);
    g_u[t*DM + d] = v * rsqrtf(ss + 1e-5f) * w[d];
}

// ---------------- generic fp32 GEMM: C[M,N] = A[M,K] @ W[N,K]^T (+=) --------
__global__ void __launch_bounds__(256) k_gemm(
    const float* __restrict__ A, const float* __restrict__ W,
    float* __restrict__ C, int M, int N, int K, int addC)
{
    __shared__ __align__(16) float As[16][68];
    __shared__ __align__(16) float Ws[16][68];
    const int bm = blockIdx.y * 64, bn = blockIdx.x * 64;
    const int tid = threadIdx.x;
    const int tx = tid & 15, ty = tid >> 4;
    const int lr = tid >> 2, lc = (tid & 3) << 2;
    float acc[4][4] = {};
    for (int k0 = 0; k0 < K; k0 += 16) {
        float4 av = make_float4(0,0,0,0), wv = make_float4(0,0,0,0);
        int am = bm + lr;
        if (am < M) av = *(const float4*)(A + (size_t)am*K + k0 + lc);
        int wn = bn + lr;
        if (wn < N) wv = *(const float4*)(W + (size_t)wn*K + k0 + lc);
        __syncthreads();
        As[lc+0][lr]=av.x; As[lc+1][lr]=av.y; As[lc+2][lr]=av.z; As[lc+3][lr]=av.w;
        Ws[lc+0][lr]=wv.x; Ws[lc+1][lr]=wv.y; Ws[lc+2][lr]=wv.z; Ws[lc+3][lr]=wv.w;
        __syncthreads();
#pragma unroll
        for (int kk = 0; kk < 16; kk++) {
            float4 a  = *(const float4*)&As[kk][ty<<2];
            float4 w4 = *(const float4*)&Ws[kk][tx<<2];
            float ar[4] = {a.x, a.y, a.z, a.w};
            float wr[4] = {w4.x, w4.y, w4.z, w4.w};
#pragma unroll
            for (int i = 0; i < 4; i++)
#pragma unroll
                for (int j = 0; j < 4; j++) acc[i][j] += ar[i] * wr[j];
        }
    }
#pragma unroll
    for (int i = 0; i < 4; i++) {
        int m = bm + (ty<<2) + i;
        if (m >= M) continue;
#pragma unroll
        for (int j = 0; j < 4; j++) {
            int n = bn + (tx<<2) + j;
            if (n >= N) continue;
            float o = acc[i][j];
            if (addC) o += C[(size_t)m*N + n];
            C[(size_t)m*N + n] = o;
        }
    }
}

// ---------------- K4: causal depthwise conv(4) + bias + silu ----------------
__global__ void __launch_bounds__(256) k_conv(
    const float* __restrict__ Wc, const float* __restrict__ bc)
{
    int idx = blockIdx.x * 256 + threadIdx.x;
    int e = idx & (ED-1);
    int bt = idx >> 9;
    int t = bt & (TT-1);
    float acc = bc[e];
#pragma unroll
    for (int j = 0; j < 4; j++) {
        int tt = t - 3 + j;
        if (tt >= 0) acc += g_xz[(size_t)(bt - 3 + j)*(2*ED) + e] * Wc[e*4 + j];
    }
    g_xc[idx] = acc / (1.f + __expf(-acc));  // silu
}

// ---------------- K6: dt_proj (K=16) + softplus ----------------
__global__ void __launch_bounds__(256) k_dt(
    const float* __restrict__ Wdt, const float* __restrict__ bdt)
{
    int t = blockIdx.x, tid = threadIdx.x;
    __shared__ float dts[16];
    if (tid < 16) dts[tid] = g_dbc[(size_t)t*48 + tid];
    __syncthreads();
#pragma unroll
    for (int r = 0; r < 2; r++) {
        int e = tid + r*256;
        float acc = bdt[e];
#pragma unroll
        for (int k = 0; k < 16; k++) acc += dts[k] * Wdt[e*16 + k];
        float sp = (acc > 20.f) ? acc : log1pf(__expf(acc));
        g_delta[(size_t)t*ED + e] = sp;
    }
}

// ---------------- K7: selective scan (lane per (b,e,n)) + gate + skip ------
__global__ void __launch_bounds__(256) k_scan(
    const float* __restrict__ A_log, const float* __restrict__ Dp)
{
    int b  = blockIdx.x >> 5;          // 32 e-groups per batch
    int eg = blockIdx.x & 31;
    int w = threadIdx.x >> 5, lane = threadIdx.x & 31;
    int half = lane >> 4, n = lane & 15;
    int e = eg*16 + w*2 + half;
    float Aen = -__expf(A_log[e*16 + n]);
    float De  = Dp[e];
    float h = 0.f;
    const float* dl  = g_delta + (size_t)b*TT*ED + e;
    const float* xcp = g_xc    + (size_t)b*TT*ED + e;
    const float* dbc = g_dbc   + (size_t)b*TT*48;
    const float* zp  = g_xz    + (size_t)b*TT*2*ED + ED + e;
    float* yp        = g_y     + (size_t)b*TT*ED + e;
    for (int t = 0; t < TT; t++) {
        float dlt = dl[(size_t)t*ED];
        float xv  = xcp[(size_t)t*ED];
        float Bn  = dbc[t*48 + 16 + n];
        float Cn  = dbc[t*48 + 32 + n];
        float dA  = __expf(dlt * Aen);
        h = dA*h + (dlt*xv)*Bn;
        float p = h * Cn;
        p += __shfl_xor_sync(0xffffffffu, p, 8);
        p += __shfl_xor_sync(0xffffffffu, p, 4);
        p += __shfl_xor_sync(0xffffffffu, p, 2);
        p += __shfl_xor_sync(0xffffffffu, p, 1);
        if (n == 0) {
            float zz = zp[(size_t)t*2*ED];
            float sz = zz / (1.f + __expf(-zz));
            yp[(size_t)t*ED] = (p + De*xv) * sz;
        }
    }
}

// ---------------- K10: final rmsnorm + head + clip + add past ----------------
__global__ void __launch_bounds__(256) k_final(
    const float* __restrict__ x, const float* __restrict__ fw,
    const float* __restrict__ hW, const float* __restrict__ hb,
    float* __restrict__ out)
{
    int t = blockIdx.x, d = threadIdx.x;
    __shared__ float red[9];
    float v = g_h[t*DM + d];
    float ss = blockReduce(v*v, red) * (1.f/DM);
    float nv = v * rsqrtf(ss + 1e-5f) * fw[d];
    float d0 = blockReduce(nv * hW[d],      red);
    float d1 = blockReduce(nv * hW[DM + d], red);
    if (d == 0) {
        float s0 = fminf(fmaxf(d0 + hb[0], -0.005f),  0.005f);
        float s1 = fminf(fmaxf(d1 + hb[1], -0.0001f), 0.0001f);
        out[t]      = x[t*INF + 4] + s0;   // past_soc = x[..., -4]
        out[BT + t] = x[t*INF + 7] + s1;   // past_soh = x[..., -1]
    }
}

extern "C" void kernel_launch(void* const* d_in, const int* in_sizes, int n_in,
                              void* d_out, int out_size)
{
    const float* x    = (const float*)d_in[0];
    const float* ipW  = (const float*)d_in[1];
    const float* ipb  = (const float*)d_in[2];
    const float* lng  = (const float*)d_in[3];
    const float* lnb  = (const float*)d_in[4];
    const float* inW  = (const float*)d_in[5];
    const float* cW   = (const float*)d_in[6];
    const float* cb   = (const float*)d_in[7];
    const float* xW   = (const float*)d_in[8];
    const float* dtW  = (const float*)d_in[9];
    const float* dtb  = (const float*)d_in[10];
    const float* Alog = (const float*)d_in[11];
    const float* Dsk  = (const float*)d_in[12];
    const float* outW = (const float*)d_in[13];
    const float* mxw  = (const float*)d_in[14];
    const float* fnw  = (const float*)d_in[15];
    const float* hW   = (const float*)d_in[16];
    const float* hb   = (const float*)d_in[17];
    float* out = (float*)d_out;

    float *u, *xz, *xc, *dbc, *y, *h;
    cudaGetSymbolAddress((void**)&h,   g_h);
    cudaGetSymbolAddress((void**)&u,   g_u);
    cudaGetSymbolAddress((void**)&xz,  g_xz);
    cudaGetSymbolAddress((void**)&xc,  g_xc);
    cudaGetSymbolAddress((void**)&dbc, g_dbc);
    cudaGetSymbolAddress((void**)&y,   g_y);

    k_input<<<BT, 256>>>(x, ipW, ipb, lng, lnb);
    for (int l = 0; l < NL; l++) {
        k_rms<<<BT, 256>>>(mxw + l*DM);
        dim3 gi((2*ED)/64, BT/64);
        k_gemm<<<gi, 256>>>(u, inW + (size_t)l*2*ED*DM, xz, BT, 2*ED, DM, 0);
        k_conv<<<(BT*ED)/256, 256>>>(cW + l*ED*4, cb + l*ED);
        dim3 gx(1, BT/64);  // N=48 fits one 64-wide tile
        k_gemm<<<gx, 256>>>(xc, xW + (size_t)l*48*ED, dbc, BT, 48, ED, 0);
        k_dt<<<BT, 256>>>(dtW + (size_t)l*ED*DTR, dtb + l*ED);
        k_scan<<<NB*32, 256>>>(Alog + (size_t)l*ED*NST, Dsk + l*ED);
        dim3 go(DM/64, BT/64);
        k_gemm<<<go, 256>>>(y, outW + (size_t)l*DM*ED, h, BT, DM, ED, 1);
    }
    k_final<<<BT, 256>>>(x, fnw, hW, hb, out);
}

// round 6
// speedup vs baseline: 1.0775x; 1.0775x over previous
#include <cuda_runtime.h>
#include <cuda_bf16.h>
#include <stdint.h>
#include <math.h>

#define NB 8
#define TT 2048
#define BT (NB*TT)
#define INF 8
#define DM 256
#define ED 512
#define NST 16
#define DTR 16
#define NL 2

// ---- fp32 scratch ----
__device__ float g_h[BT*DM];                 // residual stream
__device__ float g_xz[(size_t)BT*2*ED];      // in_proj output [xm | z]
__device__ float g_xc[(size_t)BT*ED];        // conv+silu (fp32, for scan)
__device__ float g_dbc[(size_t)BT*48];       // x_proj output: dt|B|C
__device__ float g_delta[(size_t)BT*ED];
// ---- bf16 activations (GEMM A operands) ----
__device__ __nv_bfloat16 g_uB[BT*DM];        // rmsnormed input
__device__ __nv_bfloat16 g_xcB[(size_t)BT*ED];
__device__ __nv_bfloat16 g_yB[(size_t)BT*ED];
// ---- bf16 weights ----
__device__ __nv_bfloat16 g_WinB[NL*2*ED*DM];
__device__ __nv_bfloat16 g_WxB[NL*64*ED];    // padded 48->64 rows
__device__ __nv_bfloat16 g_WoutB[NL*DM*ED];

// ---------------- block reduction (blockDim=256) ----------------
__device__ __forceinline__ float blockReduce(float v, float* red) {
    int lane = threadIdx.x & 31, w = threadIdx.x >> 5;
#pragma unroll
    for (int o = 16; o; o >>= 1) v += __shfl_xor_sync(0xffffffffu, v, o);
    __syncthreads();
    if (lane == 0) red[w] = v;
    __syncthreads();
    if (w == 0) {
        float s = (lane < 8) ? red[lane] : 0.f;
#pragma unroll
        for (int o = 4; o; o >>= 1) s += __shfl_xor_sync(0xffffffffu, s, o);
        if (lane == 0) red[8] = s;
    }
    __syncthreads();
    return red[8];
}

// ---------------- weight conversion ----------------
__global__ void __launch_bounds__(256) k_cvt(
    const float* __restrict__ s, __nv_bfloat16* __restrict__ d, int n)
{
    int i = blockIdx.x*256 + threadIdx.x;
    if (i < n) d[i] = __float2bfloat16(s[i]);
}
__global__ void __launch_bounds__(256) k_cvt_pad(
    const float* __restrict__ s, __nv_bfloat16* __restrict__ d)
{
    // d: [NL][64][512], s: [NL][48][512]
    int i = blockIdx.x*256 + threadIdx.x;  // over NL*64*512
    int k = i & 511;
    int r = (i >> 9) & 63;
    int l = i >> 15;
    float v = (r < 48) ? s[(size_t)(l*48 + r)*512 + k] : 0.f;
    d[i] = __float2bfloat16(v);
}

// ---------------- K1: input proj + layernorm ----------------
__global__ void __launch_bounds__(256) k_input(
    const float* __restrict__ x, const float* __restrict__ W,
    const float* __restrict__ bias, const float* __restrict__ g,
    const float* __restrict__ be)
{
    int t = blockIdx.x, d = threadIdx.x;
    __shared__ float xs[INF];
    __shared__ float red[9];
    if (d < INF) xs[d] = x[t*INF + d];
    __syncthreads();
    float acc = bias[d];
#pragma unroll
    for (int i = 0; i < INF; i++) acc += xs[i] * W[d*INF + i];
    float mean = blockReduce(acc, red) * (1.f/DM);
    float c = acc - mean;
    float var = blockReduce(c*c, red) * (1.f/DM);
    g_h[t*DM + d] = c * rsqrtf(var + 1e-5f) * g[d] + be[d];
}

// ---------------- K2: rmsnorm h -> uB (bf16) ----------------
__global__ void __launch_bounds__(256) k_rms(const float* __restrict__ w)
{
    int t = blockIdx.x, d = threadIdx.x;
    __shared__ float red[9];
    float v = g_h[t*DM + d];
    float ss = blockReduce(v*v, red) * (1.f/DM);
    g_uB[t*DM + d] = __float2bfloat16(v * rsqrtf(ss + 1e-5f) * w[d]);
}

// ======================= bf16 tensor-core GEMM =======================
// C[M,N] = A[M,K] @ W[N,K]^T (+= optional), A/W bf16 K-major, C fp32.
// Block tile 128x64x64, 8 warps (4x2), warp tile 32x32 via m16n8k16.

__device__ __forceinline__ void ldsm4(uint32_t* r, uint32_t addr) {
    asm volatile("ldmatrix.sync.aligned.m8n8.x4.shared.b16 {%0,%1,%2,%3},[%4];"
        : "=r"(r[0]), "=r"(r[1]), "=r"(r[2]), "=r"(r[3]) : "r"(addr));
}
__device__ __forceinline__ void mma16816(float* d,
    const uint32_t* a, uint32_t b0, uint32_t b1)
{
    asm volatile("mma.sync.aligned.m16n8k16.row.col.f32.bf16.bf16.f32 "
        "{%0,%1,%2,%3},{%4,%5,%6,%7},{%8,%9},{%0,%1,%2,%3};"
        : "+f"(d[0]), "+f"(d[1]), "+f"(d[2]), "+f"(d[3])
        : "r"(a[0]), "r"(a[1]), "r"(a[2]), "r"(a[3]), "r"(b0), "r"(b1));
}

__global__ void __launch_bounds__(256) k_gemm_tc(
    const __nv_bfloat16* __restrict__ A, const __nv_bfloat16* __restrict__ W,
    float* __restrict__ C, int M, int N, int K, int Nstore, int addC)
{
    __shared__ __align__(1024) __nv_bfloat16 As[128*64];
    __shared__ __align__(1024) __nv_bfloat16 Bs[64*64];
    const int tid = threadIdx.x;
    const int lane = tid & 31, wid = tid >> 5;
    const int wm = (wid >> 1) << 5;   // 0,32,64,96
    const int wn = (wid & 1) << 5;    // 0,32
    const int bm = blockIdx.y << 7, bn = blockIdx.x << 6;

    uint32_t sA = (uint32_t)__cvta_generic_to_shared(As);
    uint32_t sB = (uint32_t)__cvta_generic_to_shared(Bs);

    float acc[2][4][4];
#pragma unroll
    for (int i0 = 0; i0 < 2; i0++)
#pragma unroll
        for (int i1 = 0; i1 < 4; i1++)
#pragma unroll
            for (int i2 = 0; i2 < 4; i2++) acc[i0][i1][i2] = 0.f;

    // gmem 16B chunks; A tile: 128 rows x 8 chunks = 1024 -> 4/thr; B: 512 -> 2/thr
    float4 ra[4], rb[2];
#pragma unroll
    for (int i = 0; i < 4; i++) {
        int c = tid + (i << 8), row = c >> 3, ch = c & 7;
        ra[i] = *(const float4*)(A + (size_t)(bm + row)*K + (ch << 3));
    }
#pragma unroll
    for (int i = 0; i < 2; i++) {
        int c = tid + (i << 8), row = c >> 3, ch = c & 7;
        rb[i] = *(const float4*)(W + (size_t)(bn + row)*K + (ch << 3));
    }

    for (int k0 = 0; k0 < K; k0 += 64) {
        __syncthreads();
#pragma unroll
        for (int i = 0; i < 4; i++) {
            int c = tid + (i << 8), row = c >> 3, ch = c & 7;
            *(float4*)((char*)As + (row << 7) + ((ch << 4) ^ ((row & 7) << 4))) = ra[i];
        }
#pragma unroll
        for (int i = 0; i < 2; i++) {
            int c = tid + (i << 8), row = c >> 3, ch = c & 7;
            *(float4*)((char*)Bs + (row << 7) + ((ch << 4) ^ ((row & 7) << 4))) = rb[i];
        }
        __syncthreads();
        if (k0 + 64 < K) {  // prefetch next k-tile (LDG overlaps MMA)
#pragma unroll
            for (int i = 0; i < 4; i++) {
                int c = tid + (i << 8), row = c >> 3, ch = c & 7;
                ra[i] = *(const float4*)(A + (size_t)(bm + row)*K + k0 + 64 + (ch << 3));
            }
#pragma unroll
            for (int i = 0; i < 2; i++) {
                int c = tid + (i << 8), row = c >> 3, ch = c & 7;
                rb[i] = *(const float4*)(W + (size_t)(bn + row)*K + k0 + 64 + (ch << 3));
            }
        }
#pragma unroll
        for (int kk = 0; kk < 4; kk++) {
            uint32_t fa[2][4], fb[2][4];
            {
                int arow0 = wm + (lane & 15);
                uint32_t acol = (uint32_t)((kk << 5) + ((lane >> 4) << 4));
#pragma unroll
                for (int mi = 0; mi < 2; mi++) {
                    int r = arow0 + mi*16;
                    ldsm4(fa[mi], sA + (r << 7) + (acol ^ ((r & 7) << 4)));
                }
            }
            {
                int brow0 = wn + ((lane >> 4) << 3) + (lane & 7);
                uint32_t bcol = (uint32_t)((kk << 5) + (((lane >> 3) & 1) << 4));
#pragma unroll
                for (int p = 0; p < 2; p++) {
                    int r = brow0 + p*16;
                    ldsm4(fb[p], sB + (r << 7) + (bcol ^ ((r & 7) << 4)));
                }
            }
#pragma unroll
            for (int mi = 0; mi < 2; mi++)
#pragma unroll
                for (int ni = 0; ni < 4; ni++)
                    mma16816(acc[mi][ni], fa[mi],
                             fb[ni >> 1][(ni & 1)*2], fb[ni >> 1][(ni & 1)*2 + 1]);
        }
    }

    // epilogue
#pragma unroll
    for (int mi = 0; mi < 2; mi++) {
#pragma unroll
        for (int ni = 0; ni < 4; ni++) {
            int row = bm + wm + mi*16 + (lane >> 2);
            int col = bn + wn + ni*8 + ((lane & 3) << 1);
            if (col < Nstore) {
#pragma unroll
                for (int hf = 0; hf < 2; hf++) {
                    int r = row + hf*8;
                    float* Cp = C + (size_t)r*Nstore + col;
                    float v0 = acc[mi][ni][hf*2], v1 = acc[mi][ni][hf*2+1];
                    if (addC) {
                        float2 old = *(float2*)Cp;
                        v0 += old.x; v1 += old.y;
                    }
                    *(float2*)Cp = make_float2(v0, v1);
                }
            }
        }
    }
}

// ---------------- K4: causal depthwise conv(4) + bias + silu ----------------
__global__ void __launch_bounds__(256) k_conv(
    const float* __restrict__ Wc, const float* __restrict__ bc)
{
    int idx = blockIdx.x * 256 + threadIdx.x;
    int e = idx & (ED-1);
    int bt = idx >> 9;
    int t = bt & (TT-1);
    float acc = bc[e];
#pragma unroll
    for (int j = 0; j < 4; j++) {
        int tt = t - 3 + j;
        if (tt >= 0) acc += g_xz[(size_t)(bt - 3 + j)*(2*ED) + e] * Wc[e*4 + j];
    }
    float s = acc / (1.f + __expf(-acc));  // silu
    g_xc[idx] = s;
    g_xcB[idx] = __float2bfloat16(s);
}

// ---------------- K6: dt_proj (K=16) + softplus ----------------
__global__ void __launch_bounds__(256) k_dt(
    const float* __restrict__ Wdt, const float* __restrict__ bdt)
{
    int t = blockIdx.x, tid = threadIdx.x;
    __shared__ float dts[16];
    if (tid < 16) dts[tid] = g_dbc[(size_t)t*48 + tid];
    __syncthreads();
#pragma unroll
    for (int r = 0; r < 2; r++) {
        int e = tid + r*256;
        float acc = bdt[e];
#pragma unroll
        for (int k = 0; k < 16; k++) acc += dts[k] * Wdt[e*16 + k];
        float sp = (acc > 20.f) ? acc : log1pf(__expf(acc));
        g_delta[(size_t)t*ED + e] = sp;
    }
}

// ---------------- K7: selective scan + gate + skip -> yB (bf16) ------
__global__ void __launch_bounds__(256) k_scan(
    const float* __restrict__ A_log, const float* __restrict__ Dp)
{
    int b  = blockIdx.x >> 5;
    int eg = blockIdx.x & 31;
    int w = threadIdx.x >> 5, lane = threadIdx.x & 31;
    int hf = lane >> 4, n = lane & 15;
    int e = eg*16 + w*2 + hf;
    float Aen = -__expf(A_log[e*16 + n]);
    float De  = Dp[e];
    float h = 0.f;
    const float* dl  = g_delta + (size_t)b*TT*ED + e;
    const float* xcp = g_xc    + (size_t)b*TT*ED + e;
    const float* dbc = g_dbc   + (size_t)b*TT*48;
    const float* zp  = g_xz    + (size_t)b*TT*2*ED + ED + e;
    __nv_bfloat16* yp = g_yB   + (size_t)b*TT*ED + e;
    for (int t = 0; t < TT; t++) {
        float dlt = dl[(size_t)t*ED];
        float xv  = xcp[(size_t)t*ED];
        float Bn  = dbc[t*48 + 16 + n];
        float Cn  = dbc[t*48 + 32 + n];
        float dA  = __expf(dlt * Aen);
        h = dA*h + (dlt*xv)*Bn;
        float p = h * Cn;
        p += __shfl_xor_sync(0xffffffffu, p, 8);
        p += __shfl_xor_sync(0xffffffffu, p, 4);
        p += __shfl_xor_sync(0xffffffffu, p, 2);
        p += __shfl_xor_sync(0xffffffffu, p, 1);
        if (n == 0) {
            float zz = zp[(size_t)t*2*ED];
            float sz = zz / (1.f + __expf(-zz));
            yp[(size_t)t*ED] = __float2bfloat16((p + De*xv) * sz);
        }
    }
}

// ---------------- K10: final rmsnorm + head + clip + add past ----------------
__global__ void __launch_bounds__(256) k_final(
    const float* __restrict__ x, const float* __restrict__ fw,
    const float* __restrict__ hW, const float* __restrict__ hb,
    float* __restrict__ out)
{
    int t = blockIdx.x, d = threadIdx.x;
    __shared__ float red[9];
    float v = g_h[t*DM + d];
    float ss = blockReduce(v*v, red) * (1.f/DM);
    float nv = v * rsqrtf(ss + 1e-5f) * fw[d];
    float d0 = blockReduce(nv * hW[d],      red);
    float d1 = blockReduce(nv * hW[DM + d], red);
    if (d == 0) {
        float s0 = fminf(fmaxf(d0 + hb[0], -0.005f),  0.005f);
        float s1 = fminf(fmaxf(d1 + hb[1], -0.0001f), 0.0001f);
        out[t]      = x[t*INF + 4] + s0;
        out[BT + t] = x[t*INF + 7] + s1;
    }
}

extern "C" void kernel_launch(void* const* d_in, const int* in_sizes, int n_in,
                              void* d_out, int out_size)
{
    const float* x    = (const float*)d_in[0];
    const float* ipW  = (const float*)d_in[1];
    const float* ipb  = (const float*)d_in[2];
    const float* lng  = (const float*)d_in[3];
    const float* lnb  = (const float*)d_in[4];
    const float* inW  = (const float*)d_in[5];
    const float* cW   = (const float*)d_in[6];
    const float* cb   = (const float*)d_in[7];
    const float* xW   = (const float*)d_in[8];
    const float* dtW  = (const float*)d_in[9];
    const float* dtb  = (const float*)d_in[10];
    const float* Alog = (const float*)d_in[11];
    const float* Dsk  = (const float*)d_in[12];
    const float* outW = (const float*)d_in[13];
    const float* mxw  = (const float*)d_in[14];
    const float* fnw  = (const float*)d_in[15];
    const float* hW   = (const float*)d_in[16];
    const float* hb   = (const float*)d_in[17];
    float* out = (float*)d_out;

    float *xz, *xc, *dbc, *h;
    __nv_bfloat16 *uB, *xcB, *yB, *WinB, *WxB, *WoutB;
    cudaGetSymbolAddress((void**)&h,    g_h);
    cudaGetSymbolAddress((void**)&xz,   g_xz);
    cudaGetSymbolAddress((void**)&xc,   g_xc);
    cudaGetSymbolAddress((void**)&dbc,  g_dbc);
    cudaGetSymbolAddress((void**)&uB,   g_uB);
    cudaGetSymbolAddress((void**)&xcB,  g_xcB);
    cudaGetSymbolAddress((void**)&yB,   g_yB);
    cudaGetSymbolAddress((void**)&WinB, g_WinB);
    cudaGetSymbolAddress((void**)&WxB,  g_WxB);
    cudaGetSymbolAddress((void**)&WoutB,g_WoutB);

    // weight conversion (cheap, deterministic, graph-capturable)
    k_cvt<<<(NL*2*ED*DM)/256, 256>>>(inW,  WinB,  NL*2*ED*DM);
    k_cvt<<<(NL*DM*ED)/256,  256>>>(outW, WoutB, NL*DM*ED);
    k_cvt_pad<<<(NL*64*ED)/256, 256>>>(xW, WxB);

    k_input<<<BT, 256>>>(x, ipW, ipb, lng, lnb);
    for (int l = 0; l < NL; l++) {
        k_rms<<<BT, 256>>>(mxw + l*DM);
        dim3 gi((2*ED)/64, BT/128);
        k_gemm_tc<<<gi, 256>>>(uB, WinB + (size_t)l*2*ED*DM, xz, BT, 2*ED, DM, 2*ED, 0);
        k_conv<<<(BT*ED)/256, 256>>>(cW + l*ED*4, cb + l*ED);
        dim3 gx(1, BT/128);
        k_gemm_tc<<<gx, 256>>>(xcB, WxB + (size_t)l*64*ED, dbc, BT, 64, ED, 48, 0);
        k_dt<<<BT, 256>>>(dtW + (size_t)l*ED*DTR, dtb + l*ED);
        k_scan<<<NB*32, 256>>>(Alog + (size_t)l*ED*NST, Dsk + l*ED);
        dim3 go(DM/64, BT/128);
        k_gemm_tc<<<go, 256>>>(yB, WoutB + (size_t)l*DM*ED, h, BT, DM, ED, DM, 1);
    }
    k_final<<<BT, 256>>>(x, fnw, hW, hb, out);
}